// round 12
// baseline (speedup 1.0000x reference)
#include <cuda_runtime.h>
#include <cuda_fp16.h>
#include <cstdint>

// Problem dims: B=8, T=2048 -> N=16384 tokens, D=512, E=8, H=1024, top_k=2
#define N_TOK   16384
#define D_DIM   512
#define E_EXP   8
#define H_DIM   1024
#define NPAIR   (2 * N_TOK)
#define RBLK    (N_TOK / 8)

#define BM 128
#define BN 128
#define KCH 64                       // 64 fp16 = 128B of data per row per chunk
#define ROWB 144                     // smem row stride (128B data + 16B pad)
#define TILE_BYTES (128 * ROWB)      // 18432
#define STAGE_BYTES (2 * TILE_BYTES) // A, B = 36864
#define NSTAGE 3
#define SMEM_DYN (1024 + NSTAGE * STAGE_BYTES)   // 111616 B (2 CTAs/SM: 223232 <= 227KB)
#define MAXTILE 264                  // >= 256 + (E_EXP-1) possible ragged tiles

// ---------------- scratch (static device globals) ----------------
__device__ __align__(1024) __half g_xq[(size_t)N_TOK * D_DIM];
__device__ __align__(1024) __half g_w1q[(size_t)E_EXP * H_DIM * D_DIM]; // [E][H][D] K-major
__device__ __align__(1024) __half g_w2q[(size_t)E_EXP * D_DIM * H_DIM]; // [E][D][H] K-major
__device__ __align__(1024) __half g_hq[(size_t)NPAIR * H_DIM];
__device__ __align__(1024) float g_out2[(size_t)NPAIR * D_DIM];
__device__ int   g_tok[NPAIR];
__device__ float g_w[NPAIR];
__device__ int   g_slot[NPAIR];
__device__ int   g_topi[NPAIR];
__device__ float g_topw[NPAIR];
__device__ int   g_cnt[E_EXP];
__device__ int   g_cnt2[E_EXP];
__device__ int   g_off[E_EXP];
__device__ int   g_toff[E_EXP + 1];              // tile prefix (ceil(cnt/BM))
__device__ float g_psums[RBLK * E_EXP];

// ---------------- PTX helpers (baseline ISA only) ----------------
__device__ __forceinline__ uint32_t smem_u32(const void* p) {
    uint32_t a;
    asm("{ .reg .u64 t; cvta.to.shared.u64 t, %1; cvt.u32.u64 %0, t; }" : "=r"(a) : "l"(p));
    return a;
}
__device__ __forceinline__ void cp16(uint32_t dst, const void* src) {
    asm volatile("cp.async.cg.shared.global [%0], [%1], 16;" :: "r"(dst), "l"(src));
}
__device__ __forceinline__ void ldsm4(uint32_t* r, uint32_t addr) {
    asm volatile("ldmatrix.sync.aligned.m8n8.x4.shared.b16 {%0,%1,%2,%3}, [%4];"
                 : "=r"(r[0]), "=r"(r[1]), "=r"(r[2]), "=r"(r[3]) : "r"(addr));
}
__device__ __forceinline__ void mma_f16(float* c, const uint32_t* a, uint32_t b0, uint32_t b1) {
    asm volatile(
        "mma.sync.aligned.m16n8k16.row.col.f32.f16.f16.f32 "
        "{%0,%1,%2,%3}, {%4,%5,%6,%7}, {%8,%9}, {%0,%1,%2,%3};"
        : "+f"(c[0]), "+f"(c[1]), "+f"(c[2]), "+f"(c[3])
        : "r"(a[0]), "r"(a[1]), "r"(a[2]), "r"(a[3]), "r"(b0), "r"(b1));
}

// ---------------- init ----------------
__global__ void init_kernel() {
    int t = threadIdx.x;
    if (t < E_EXP) { g_cnt[t] = 0; g_cnt2[t] = 0; }
}

// ---------------- router (fused with x -> fp16 conversion) ----------------
__global__ void router_kernel(const float* __restrict__ x,
                              const float* __restrict__ Wr,
                              const float* __restrict__ br) {
    __shared__ float ps[8][E_EXP];
    const int wid = threadIdx.x >> 5, lane = threadIdx.x & 31;
    const int n = blockIdx.x * 8 + wid;
    const float4* xr = (const float4*)(x + (size_t)n * D_DIM);

    // each lane handles 16 contiguous floats (4 float4): indices lane*16 .. lane*16+15
    float4 v[4];
    float acc[E_EXP];
#pragma unroll
    for (int e = 0; e < E_EXP; e++) acc[e] = 0.f;
#pragma unroll
    for (int i = 0; i < 4; i++) {
        v[i] = xr[lane * 4 + i];
        const float* w = Wr + (lane * 16 + i * 4) * E_EXP;
        const float vv[4] = {v[i].x, v[i].y, v[i].z, v[i].w};
#pragma unroll
        for (int j = 0; j < 4; j++)
#pragma unroll
            for (int e = 0; e < E_EXP; e++) acc[e] += vv[j] * w[j * E_EXP + e];
    }
    // emit fp16 copy of x
    uint2 pk[2];
    {
        unsigned short s[16];
#pragma unroll
        for (int i = 0; i < 4; i++) {
            s[4 * i + 0] = __half_as_ushort(__float2half_rn(v[i].x));
            s[4 * i + 1] = __half_as_ushort(__float2half_rn(v[i].y));
            s[4 * i + 2] = __half_as_ushort(__float2half_rn(v[i].z));
            s[4 * i + 3] = __half_as_ushort(__float2half_rn(v[i].w));
        }
        pk[0] = make_uint2((uint32_t)s[0] | ((uint32_t)s[1] << 16) | 0u,
                           (uint32_t)s[2] | ((uint32_t)s[3] << 16));
        pk[0].x = (uint32_t)s[0] | ((uint32_t)s[1] << 16);
        pk[0].y = (uint32_t)s[2] | ((uint32_t)s[3] << 16);
        uint2* dst = (uint2*)(g_xq + (size_t)n * D_DIM);
        dst[lane * 4 + 0] = make_uint2((uint32_t)s[0] | ((uint32_t)s[1] << 16),
                                       (uint32_t)s[2] | ((uint32_t)s[3] << 16));
        dst[lane * 4 + 1] = make_uint2((uint32_t)s[4] | ((uint32_t)s[5] << 16),
                                       (uint32_t)s[6] | ((uint32_t)s[7] << 16));
        dst[lane * 4 + 2] = make_uint2((uint32_t)s[8] | ((uint32_t)s[9] << 16),
                                       (uint32_t)s[10] | ((uint32_t)s[11] << 16));
        dst[lane * 4 + 3] = make_uint2((uint32_t)s[12] | ((uint32_t)s[13] << 16),
                                       (uint32_t)s[14] | ((uint32_t)s[15] << 16));
    }

#pragma unroll
    for (int e = 0; e < E_EXP; e++)
#pragma unroll
        for (int o = 16; o > 0; o >>= 1)
            acc[e] += __shfl_xor_sync(0xffffffffu, acc[e], o);

    if (lane == 0) {
        float mx = -1e30f;
#pragma unroll
        for (int e = 0; e < E_EXP; e++) { acc[e] += br[e]; mx = fmaxf(mx, acc[e]); }
        float s = 0.f;
#pragma unroll
        for (int e = 0; e < E_EXP; e++) { acc[e] = expf(acc[e] - mx); s += acc[e]; }
        const float inv = 1.f / s;
        float p1 = -1.f, p2 = -1.f; int i1 = 0, i2 = 0;
#pragma unroll
        for (int e = 0; e < E_EXP; e++) {
            float p = acc[e] * inv;
            ps[wid][e] = p;
            if (p > p1)      { p2 = p1; i2 = i1; p1 = p; i1 = e; }
            else if (p > p2) { p2 = p; i2 = e; }
        }
        g_topi[2 * n] = i1;     g_topw[2 * n] = p1;
        g_topi[2 * n + 1] = i2; g_topw[2 * n + 1] = p2;
        atomicAdd(&g_cnt[i1], 1);
        atomicAdd(&g_cnt[i2], 1);
    }
    __syncthreads();
    if (threadIdx.x < E_EXP) {
        float s = 0.f;
#pragma unroll
        for (int w = 0; w < 8; w++) s += ps[w][threadIdx.x];
        g_psums[blockIdx.x * E_EXP + threadIdx.x] = s;
    }
}

// ---------------- offsets + tile prefix + gating loss ----------------
__global__ void offsets_loss_kernel(float* __restrict__ out, int out_size) {
    __shared__ float dsq[E_EXP];
    const int tid = threadIdx.x;
    if (tid == 0) {
        int o = 0, t = 0;
        for (int e = 0; e < E_EXP; e++) {
            g_off[e] = o;
            g_toff[e] = t;
            o += g_cnt[e];
            t += (g_cnt[e] + BM - 1) / BM;
        }
        g_toff[E_EXP] = t;
    }
    const int wid = tid >> 5, lane = tid & 31;
    if (wid < E_EXP) {
        float s = 0.f;
        for (int b = lane; b < RBLK; b += 32) s += g_psums[b * E_EXP + wid];
#pragma unroll
        for (int o = 16; o > 0; o >>= 1) s += __shfl_xor_sync(0xffffffffu, s, o);
        if (lane == 0) {
            float mean = s / (float)N_TOK;
            float d = (1.0f / E_EXP) - mean;
            dsq[wid] = d * d;
        }
    }
    __syncthreads();
    if (tid == 0 && out_size > N_TOK * D_DIM) {
        float l = 0.f;
        for (int e = 0; e < E_EXP; e++) l += dsq[e];
        out[N_TOK * D_DIM] = (l / E_EXP) * 1e-4f;
    }
}

// ---------------- scatter ----------------
__global__ void scatter_kernel() {
    const int n = blockIdx.x * blockDim.x + threadIdx.x;
    if (n >= N_TOK) return;
#pragma unroll
    for (int k = 0; k < 2; k++) {
        int e = g_topi[2 * n + k];
        int i = atomicAdd(&g_cnt2[e], 1);
        int p = g_off[e] + i;
        g_tok[p] = n;
        g_w[p] = g_topw[2 * n + k];
        g_slot[2 * n + k] = p;
    }
}

// ---------------- weight transpose to fp16: [E][K][N] fp32 -> [E][N][K] fp16 ----------------
// Tq MUST be the real device address (cudaGetSymbolAddress) — host shadow is silently
// ATS-writable on GB300 and the device array would stay zero (R3/R4 bug).
template <int K, int N>
__global__ void transpose_half_kernel(const float* __restrict__ W,
                                      __half* __restrict__ Tq) {
    __shared__ float t[32][33];
    const int e = blockIdx.z;
    const int n0 = blockIdx.x * 32, k0 = blockIdx.y * 32;
    const int tx = threadIdx.x, ty = threadIdx.y;
    for (int i = ty; i < 32; i += 8)
        t[i][tx] = W[((size_t)e * K + k0 + i) * N + n0 + tx];
    __syncthreads();
    for (int i = ty; i < 32; i += 8) {
        float v = t[tx][i];                       // = in[k0+tx][n0+i]
        Tq[((size_t)e * N + n0 + i) * K + k0 + tx] = __float2half_rn(v);
    }
}

// ---------------- fp16 single-plane GEMM via mma.m16n8k16.f16 + ldmatrix ----------------
// Flattened grid: blockIdx.y = global m-tile over expert segments (g_toff mapping).
// PASS2=false: h = leaky(gather(xq) @ W1q^T + b1) -> g_hq (fp16), KDIM=512,  NCOL=1024
// PASS2=true : o = w * leaky(hq @ W2q^T + b2)     -> g_out2,      KDIM=1024, NCOL=512
template <bool PASS2, int KDIM, int NCOL>
__global__ void __launch_bounds__(256, 2)
gemm_f16(const float* __restrict__ bias) {
    extern __shared__ char smem[];
    const int ty = blockIdx.y;
    if (ty >= g_toff[E_EXP]) return;
    int e = 0;
#pragma unroll
    for (int i = 1; i < E_EXP; i++) if (ty >= g_toff[i]) e = i;
    const int cnt = g_cnt[e];
    const int m0 = (ty - g_toff[e]) * BM;
    const int n0 = blockIdx.x * BN;
    const int off = g_off[e];
    const int tid = threadIdx.x;
    const int wid = tid >> 5, lane = tid & 31;
    const int warp_m = wid >> 2;                 // 0..1 (64 rows)
    const int warp_n = wid & 3;                  // 0..3 (32 cols)
    const int qr = lane >> 2;                    // 0..7
    const int qc = (lane & 3) * 2;               // k/col element pair base

    const uint32_t sbase = smem_u32(smem);
    int* toks = (int*)smem;                      // [0,512)
    const uint32_t TILE0 = 1024;

    if (!PASS2) {
        if (tid < BM) {
            int m = m0 + tid;
            toks[tid] = g_tok[off + (m < cnt ? m : cnt - 1)];
        }
        __syncthreads();
    }

    const char* Aqb = (const char*)(PASS2 ? g_hq : g_xq);
    const char* Bqb = (const char*)(PASS2 ? g_w2q : g_w1q);

    // cp.async plan: 4 units of 16B per tile type (128 rows x 8 units)
    size_t aoff[4], boff[4];
    uint32_t dst[4];
#pragma unroll
    for (int t = 0; t < 4; t++) {
        int uu = tid + 256 * t;
        int r = uu >> 3, u = uu & 7;
        dst[t] = (uint32_t)(r * ROWB + u * 16);
        if (!PASS2) {
            aoff[t] = ((size_t)toks[r] * KDIM) * 2 + u * 16;
        } else {
            int m = m0 + r;
            int row = off + (m < cnt ? m : cnt - 1);
            aoff[t] = ((size_t)row * KDIM) * 2 + u * 16;
        }
        boff[t] = ((size_t)(e * NCOL + n0 + r) * KDIM) * 2 + u * 16;
    }

    auto issue_loads = [&](int c, int s) {
        const uint32_t st = sbase + TILE0 + s * STAGE_BYTES;
        const size_t kb = (size_t)c * (KCH * 2);
#pragma unroll
        for (int t = 0; t < 4; t++) {
            cp16(st + dst[t],              Aqb + aoff[t] + kb);
            cp16(st + TILE_BYTES + dst[t], Bqb + boff[t] + kb);
        }
        asm volatile("cp.async.commit_group;" ::: "memory");
    };

    float acc[4][4][4];
#pragma unroll
    for (int f = 0; f < 4; f++)
#pragma unroll
        for (int g = 0; g < 4; g++)
#pragma unroll
            for (int q = 0; q < 4; q++) acc[f][g][q] = 0.f;

    constexpr int C = KDIM / KCH;
    issue_loads(0, 0);
    issue_loads(1, 1);

    // ldmatrix per-thread base offsets (within a tile; add stage base + ks*32)
    uint32_t aBase[4];
#pragma unroll
    for (int f = 0; f < 4; f++)
        aBase[f] = (uint32_t)((warp_m * 64 + f * 16 + (lane & 15)) * ROWB + (lane >> 4) * 16);
    uint32_t bBase[2];
#pragma unroll
    for (int p = 0; p < 2; p++)
        bBase[p] = (uint32_t)((warp_n * 32 + p * 16 + ((lane >> 4) & 1) * 8 + (lane & 7)) * ROWB
                              + ((lane >> 3) & 1) * 16);

    for (int c = 0; c < C; c++) {
        const int s = c % NSTAGE;
        if (c == C - 1) asm volatile("cp.async.wait_group 0;" ::: "memory");
        else            asm volatile("cp.async.wait_group 1;" ::: "memory");
        __syncthreads();                         // single barrier per chunk (tail one is redundant)
        if (c + 2 < C) issue_loads(c + 2, (c + 2) % NSTAGE);

        const uint32_t stA = sbase + TILE0 + s * STAGE_BYTES;
        const uint32_t stB = stA + TILE_BYTES;

#pragma unroll
        for (int ks = 0; ks < 4; ks++) {
            const uint32_t ko = (uint32_t)(ks * 32);
            uint32_t aq[4][4], bq[2][4];
#pragma unroll
            for (int f = 0; f < 4; f++) ldsm4(aq[f], stA + aBase[f] + ko);
#pragma unroll
            for (int p = 0; p < 2; p++) ldsm4(bq[p], stB + bBase[p] + ko);
#pragma unroll
            for (int f = 0; f < 4; f++)
#pragma unroll
                for (int p = 0; p < 2; p++) {
                    mma_f16(acc[f][2 * p],     aq[f], bq[p][0], bq[p][1]);
                    mma_f16(acc[f][2 * p + 1], aq[f], bq[p][2], bq[p][3]);
                }
        }
    }

    // ---- epilogue: bias + leaky (+wgt / fp16 round), direct stores ----
    const float* bb = bias + e * NCOL + n0;
#pragma unroll
    for (int f = 0; f < 4; f++) {
        const int rbase = warp_m * 64 + f * 16 + qr;
#pragma unroll
        for (int half = 0; half < 2; half++) {
            const int row = rbase + half * 8;
            const int m = m0 + row;
            if (m >= cnt) continue;
            const int grow = off + m;
            float wgt = 0.f;
            if (PASS2) wgt = g_w[grow];
#pragma unroll
            for (int g = 0; g < 4; g++) {
                const int col = warp_n * 32 + g * 8 + qc;
                float v0 = acc[f][g][2 * half + 0] + bb[col];
                float v1 = acc[f][g][2 * half + 1] + bb[col + 1];
                v0 = (v0 > 0.f) ? v0 : 0.01f * v0;
                v1 = (v1 > 0.f) ? v1 : 0.01f * v1;
                const size_t base = (size_t)grow * NCOL + n0 + col;
                if (!PASS2) {
                    *(uint32_t*)&g_hq[base] =
                        (uint32_t)__half_as_ushort(__float2half_rn(v0)) |
                        ((uint32_t)__half_as_ushort(__float2half_rn(v1)) << 16);
                } else {
                    *(float2*)&g_out2[base] = make_float2(wgt * v0, wgt * v1);
                }
            }
        }
    }
}

// ---------------- combine ----------------
__global__ void combine_kernel(float* __restrict__ out) {
    const int t = blockIdx.x * blockDim.x + threadIdx.x;
    if (t >= N_TOK * (D_DIM / 4)) return;
    const int n = t / (D_DIM / 4);
    const int d = (t % (D_DIM / 4)) * 4;
    const int s0 = g_slot[2 * n], s1 = g_slot[2 * n + 1];
    float4 a = *(const float4*)(g_out2 + (size_t)s0 * D_DIM + d);
    float4 b = *(const float4*)(g_out2 + (size_t)s1 * D_DIM + d);
    float4 r; r.x = a.x + b.x; r.y = a.y + b.y; r.z = a.z + b.z; r.w = a.w + b.w;
    *(float4*)(out + (size_t)n * D_DIM + d) = r;
}

extern "C" void kernel_launch(void* const* d_in, const int* in_sizes, int n_in,
                              void* d_out, int out_size) {
    const float* x  = (const float*)d_in[0];
    const float* Wr = (const float*)d_in[1];
    const float* br = (const float*)d_in[2];
    const float* W1 = (const float*)d_in[3];
    const float* b1 = (const float*)d_in[4];
    const float* W2 = (const float*)d_in[5];
    const float* b2 = (const float*)d_in[6];
    float* out = (float*)d_out;

    cudaFuncSetAttribute(gemm_f16<false, D_DIM, H_DIM>,
                         cudaFuncAttributeMaxDynamicSharedMemorySize, SMEM_DYN);
    cudaFuncSetAttribute(gemm_f16<true, H_DIM, D_DIM>,
                         cudaFuncAttributeMaxDynamicSharedMemorySize, SMEM_DYN);

    // REAL device addresses of __device__ scratch (never pass symbols from host!)
    __half *w1q, *w2q;
    cudaGetSymbolAddress((void**)&w1q, g_w1q);
    cudaGetSymbolAddress((void**)&w2q, g_w2q);

    init_kernel<<<1, 32>>>();
    router_kernel<<<RBLK, 256>>>(x, Wr, br);
    offsets_loss_kernel<<<1, 256>>>(out, out_size);
    scatter_kernel<<<(N_TOK + 255) / 256, 256>>>();
    transpose_half_kernel<D_DIM, H_DIM>
        <<<dim3(H_DIM / 32, D_DIM / 32, E_EXP), dim3(32, 8)>>>(W1, w1q);
    transpose_half_kernel<H_DIM, D_DIM>
        <<<dim3(D_DIM / 32, H_DIM / 32, E_EXP), dim3(32, 8)>>>(W2, w2q);

    gemm_f16<false, D_DIM, H_DIM>
        <<<dim3(H_DIM / BN, MAXTILE, 1), 256, SMEM_DYN>>>(b1);
    gemm_f16<true, H_DIM, D_DIM>
        <<<dim3(D_DIM / BN, MAXTILE, 1), 256, SMEM_DYN>>>(b2);
    combine_kernel<<<(N_TOK * D_DIM / 4 + 255) / 256, 256>>>(out);
}

// round 13
// speedup vs baseline: 1.4698x; 1.4698x over previous
#include <cuda_runtime.h>
#include <cuda_fp16.h>
#include <cstdint>

// Problem dims: B=8, T=2048 -> N=16384 tokens, D=512, E=8, H=1024, top_k=2
#define N_TOK   16384
#define D_DIM   512
#define E_EXP   8
#define H_DIM   1024
#define NPAIR   (2 * N_TOK)
#define RBLK    (N_TOK / 8)

#define BM 128
#define BN 128
#define KCH 64                       // 64 fp16 = 128B of data per row per chunk
#define ROWB 144                     // smem row stride (128B data + 16B pad)
#define TILE_BYTES (128 * ROWB)      // 18432
#define STAGE_BYTES (2 * TILE_BYTES) // A, B = 36864
#define NSTAGE 3
#define SMEM_DYN (1024 + NSTAGE * STAGE_BYTES)   // 111616 B (2 CTAs/SM: 223232 <= 227KB)
#define MAXTILE 264                  // >= 256 + (E_EXP-1) possible ragged tiles

// ---------------- scratch (static device globals) ----------------
__device__ __align__(1024) __half g_xq[(size_t)N_TOK * D_DIM];
__device__ __align__(1024) __half g_w1q[(size_t)E_EXP * H_DIM * D_DIM]; // [E][H][D] K-major
__device__ __align__(1024) __half g_w2q[(size_t)E_EXP * D_DIM * H_DIM]; // [E][D][H] K-major
__device__ __align__(1024) __half g_hq[(size_t)NPAIR * H_DIM];
__device__ __align__(1024) float g_out2[(size_t)NPAIR * D_DIM];
__device__ int   g_tok[NPAIR];
__device__ float g_w[NPAIR];
__device__ int   g_slot[NPAIR];
__device__ int   g_topi[NPAIR];
__device__ float g_topw[NPAIR];
__device__ int   g_cnt[E_EXP];
__device__ int   g_cnt2[E_EXP];
__device__ int   g_off[E_EXP];
__device__ int   g_toff[E_EXP + 1];              // tile prefix (ceil(cnt/BM))
__device__ float g_psums[RBLK * E_EXP];

// ---------------- PTX helpers (baseline ISA only) ----------------
__device__ __forceinline__ uint32_t smem_u32(const void* p) {
    uint32_t a;
    asm("{ .reg .u64 t; cvta.to.shared.u64 t, %1; cvt.u32.u64 %0, t; }" : "=r"(a) : "l"(p));
    return a;
}
__device__ __forceinline__ void cp16(uint32_t dst, const void* src) {
    asm volatile("cp.async.cg.shared.global [%0], [%1], 16;" :: "r"(dst), "l"(src));
}
__device__ __forceinline__ void ldsm4(uint32_t* r, uint32_t addr) {
    asm volatile("ldmatrix.sync.aligned.m8n8.x4.shared.b16 {%0,%1,%2,%3}, [%4];"
                 : "=r"(r[0]), "=r"(r[1]), "=r"(r[2]), "=r"(r[3]) : "r"(addr));
}
__device__ __forceinline__ void mma_f16(float* c, const uint32_t* a, uint32_t b0, uint32_t b1) {
    asm volatile(
        "mma.sync.aligned.m16n8k16.row.col.f32.f16.f16.f32 "
        "{%0,%1,%2,%3}, {%4,%5,%6,%7}, {%8,%9}, {%0,%1,%2,%3};"
        : "+f"(c[0]), "+f"(c[1]), "+f"(c[2]), "+f"(c[3])
        : "r"(a[0]), "r"(a[1]), "r"(a[2]), "r"(a[3]), "r"(b0), "r"(b1));
}

// ---------------- init ----------------
__global__ void init_kernel() {
    int t = threadIdx.x;
    if (t < E_EXP) { g_cnt[t] = 0; g_cnt2[t] = 0; }
}

// ---------------- router (R9 coalesced version) ----------------
__global__ void router_kernel(const float* __restrict__ x,
                              const float* __restrict__ Wr,
                              const float* __restrict__ br) {
    __shared__ float ps[8][E_EXP];
    const int wid = threadIdx.x >> 5, lane = threadIdx.x & 31;
    const int n = blockIdx.x * 8 + wid;
    const float* xr = x + (size_t)n * D_DIM;
    float acc[E_EXP];
#pragma unroll
    for (int e = 0; e < E_EXP; e++) acc[e] = 0.f;
    for (int i = lane; i < D_DIM; i += 32) {
        float xv = xr[i];
        const float* w = Wr + i * E_EXP;
#pragma unroll
        for (int e = 0; e < E_EXP; e++) acc[e] += xv * w[e];
    }
#pragma unroll
    for (int e = 0; e < E_EXP; e++)
#pragma unroll
        for (int o = 16; o > 0; o >>= 1)
            acc[e] += __shfl_xor_sync(0xffffffffu, acc[e], o);

    if (lane == 0) {
        float mx = -1e30f;
#pragma unroll
        for (int e = 0; e < E_EXP; e++) { acc[e] += br[e]; mx = fmaxf(mx, acc[e]); }
        float s = 0.f;
#pragma unroll
        for (int e = 0; e < E_EXP; e++) { acc[e] = expf(acc[e] - mx); s += acc[e]; }
        const float inv = 1.f / s;
        float p1 = -1.f, p2 = -1.f; int i1 = 0, i2 = 0;
#pragma unroll
        for (int e = 0; e < E_EXP; e++) {
            float p = acc[e] * inv;
            ps[wid][e] = p;
            if (p > p1)      { p2 = p1; i2 = i1; p1 = p; i1 = e; }
            else if (p > p2) { p2 = p; i2 = e; }
        }
        g_topi[2 * n] = i1;     g_topw[2 * n] = p1;
        g_topi[2 * n + 1] = i2; g_topw[2 * n + 1] = p2;
        atomicAdd(&g_cnt[i1], 1);
        atomicAdd(&g_cnt[i2], 1);
    }
    __syncthreads();
    if (threadIdx.x < E_EXP) {
        float s = 0.f;
#pragma unroll
        for (int w = 0; w < 8; w++) s += ps[w][threadIdx.x];
        g_psums[blockIdx.x * E_EXP + threadIdx.x] = s;
    }
}

// ---------------- offsets + tile prefix + gating loss ----------------
__global__ void offsets_loss_kernel(float* __restrict__ out, int out_size) {
    __shared__ float dsq[E_EXP];
    const int tid = threadIdx.x;
    if (tid == 0) {
        int o = 0, t = 0;
        for (int e = 0; e < E_EXP; e++) {
            g_off[e] = o;
            g_toff[e] = t;
            o += g_cnt[e];
            t += (g_cnt[e] + BM - 1) / BM;
        }
        g_toff[E_EXP] = t;
    }
    const int wid = tid >> 5, lane = tid & 31;
    if (wid < E_EXP) {
        float s = 0.f;
        for (int b = lane; b < RBLK; b += 32) s += g_psums[b * E_EXP + wid];
#pragma unroll
        for (int o = 16; o > 0; o >>= 1) s += __shfl_xor_sync(0xffffffffu, s, o);
        if (lane == 0) {
            float mean = s / (float)N_TOK;
            float d = (1.0f / E_EXP) - mean;
            dsq[wid] = d * d;
        }
    }
    __syncthreads();
    if (tid == 0 && out_size > N_TOK * D_DIM) {
        float l = 0.f;
        for (int e = 0; e < E_EXP; e++) l += dsq[e];
        out[N_TOK * D_DIM] = (l / E_EXP) * 1e-4f;
    }
}

// ---------------- scatter ----------------
__global__ void scatter_kernel() {
    const int n = blockIdx.x * blockDim.x + threadIdx.x;
    if (n >= N_TOK) return;
#pragma unroll
    for (int k = 0; k < 2; k++) {
        int e = g_topi[2 * n + k];
        int i = atomicAdd(&g_cnt2[e], 1);
        int p = g_off[e] + i;
        g_tok[p] = n;
        g_w[p] = g_topw[2 * n + k];
        g_slot[2 * n + k] = p;
    }
}

// ---------------- x -> fp16 (separate, coalesced) ----------------
__global__ void convert_x_kernel(const float* __restrict__ x) {
    const int i = blockIdx.x * blockDim.x + threadIdx.x;
    if (i >= N_TOK * D_DIM / 4) return;
    float4 v = ((const float4*)x)[i];
    unsigned short s0 = __half_as_ushort(__float2half_rn(v.x));
    unsigned short s1 = __half_as_ushort(__float2half_rn(v.y));
    unsigned short s2 = __half_as_ushort(__float2half_rn(v.z));
    unsigned short s3 = __half_as_ushort(__float2half_rn(v.w));
    ((uint2*)g_xq)[i] = make_uint2((uint32_t)s0 | ((uint32_t)s1 << 16),
                                   (uint32_t)s2 | ((uint32_t)s3 << 16));
}

// ---------------- weight transpose to fp16: [E][K][N] fp32 -> [E][N][K] fp16 ----------------
// Tq MUST be the real device address (cudaGetSymbolAddress) — host shadow is silently
// ATS-writable on GB300 and the device array would stay zero (R3/R4 bug).
template <int K, int N>
__global__ void transpose_half_kernel(const float* __restrict__ W,
                                      __half* __restrict__ Tq) {
    __shared__ float t[32][33];
    const int e = blockIdx.z;
    const int n0 = blockIdx.x * 32, k0 = blockIdx.y * 32;
    const int tx = threadIdx.x, ty = threadIdx.y;
    for (int i = ty; i < 32; i += 8)
        t[i][tx] = W[((size_t)e * K + k0 + i) * N + n0 + tx];
    __syncthreads();
    for (int i = ty; i < 32; i += 8) {
        float v = t[tx][i];                       // = in[k0+tx][n0+i]
        Tq[((size_t)e * N + n0 + i) * K + k0 + tx] = __float2half_rn(v);
    }
}

// ---------------- fp16 single-plane GEMM via mma.m16n8k16.f16 + ldmatrix ----------------
// Flattened grid: blockIdx.y = global m-tile over expert segments (g_toff mapping).
// PASS2=false: h = leaky(gather(xq) @ W1q^T + b1) -> g_hq (fp16), KDIM=512,  NCOL=1024
// PASS2=true : o = w * leaky(hq @ W2q^T + b2)     -> g_out2,      KDIM=1024, NCOL=512
template <bool PASS2, int KDIM, int NCOL>
__global__ void __launch_bounds__(256, 2)
gemm_f16(const float* __restrict__ bias) {
    extern __shared__ char smem[];
    const int ty = blockIdx.y;
    if (ty >= g_toff[E_EXP]) return;
    int e = 0;
#pragma unroll
    for (int i = 1; i < E_EXP; i++) if (ty >= g_toff[i]) e = i;
    const int cnt = g_cnt[e];
    const int m0 = (ty - g_toff[e]) * BM;
    const int n0 = blockIdx.x * BN;
    const int off = g_off[e];
    const int tid = threadIdx.x;
    const int wid = tid >> 5, lane = tid & 31;
    const int warp_m = wid >> 2;                 // 0..1 (64 rows)
    const int warp_n = wid & 3;                  // 0..3 (32 cols)
    const int qr = lane >> 2;                    // 0..7
    const int qc = (lane & 3) * 2;               // k/col element pair base

    const uint32_t sbase = smem_u32(smem);
    int* toks = (int*)smem;                      // [0,512)
    const uint32_t TILE0 = 1024;

    if (!PASS2) {
        if (tid < BM) {
            int m = m0 + tid;
            toks[tid] = g_tok[off + (m < cnt ? m : cnt - 1)];
        }
        __syncthreads();
    }

    const char* Aqb = (const char*)(PASS2 ? g_hq : g_xq);
    const char* Bqb = (const char*)(PASS2 ? g_w2q : g_w1q);

    // cp.async plan: 4 units of 16B per tile type (128 rows x 8 units)
    size_t aoff[4], boff[4];
    uint32_t dst[4];
#pragma unroll
    for (int t = 0; t < 4; t++) {
        int uu = tid + 256 * t;
        int r = uu >> 3, u = uu & 7;
        dst[t] = (uint32_t)(r * ROWB + u * 16);
        if (!PASS2) {
            aoff[t] = ((size_t)toks[r] * KDIM) * 2 + u * 16;
        } else {
            int m = m0 + r;
            int row = off + (m < cnt ? m : cnt - 1);
            aoff[t] = ((size_t)row * KDIM) * 2 + u * 16;
        }
        boff[t] = ((size_t)(e * NCOL + n0 + r) * KDIM) * 2 + u * 16;
    }

    auto issue_loads = [&](int c, int s) {
        const uint32_t st = sbase + TILE0 + s * STAGE_BYTES;
        const size_t kb = (size_t)c * (KCH * 2);
#pragma unroll
        for (int t = 0; t < 4; t++) {
            cp16(st + dst[t],              Aqb + aoff[t] + kb);
            cp16(st + TILE_BYTES + dst[t], Bqb + boff[t] + kb);
        }
        asm volatile("cp.async.commit_group;" ::: "memory");
    };

    float acc[4][4][4];
#pragma unroll
    for (int f = 0; f < 4; f++)
#pragma unroll
        for (int g = 0; g < 4; g++)
#pragma unroll
            for (int q = 0; q < 4; q++) acc[f][g][q] = 0.f;

    constexpr int C = KDIM / KCH;
    issue_loads(0, 0);
    issue_loads(1, 1);

    // ldmatrix per-thread base offsets (within a tile; add stage base + ks*32)
    uint32_t aBase[4];
#pragma unroll
    for (int f = 0; f < 4; f++)
        aBase[f] = (uint32_t)((warp_m * 64 + f * 16 + (lane & 15)) * ROWB + (lane >> 4) * 16);
    uint32_t bBase[2];
#pragma unroll
    for (int p = 0; p < 2; p++)
        bBase[p] = (uint32_t)((warp_n * 32 + p * 16 + ((lane >> 4) & 1) * 8 + (lane & 7)) * ROWB
                              + ((lane >> 3) & 1) * 16);

    for (int c = 0; c < C; c++) {
        const int s = c % NSTAGE;
        if (c == C - 1) asm volatile("cp.async.wait_group 0;" ::: "memory");
        else            asm volatile("cp.async.wait_group 1;" ::: "memory");
        __syncthreads();                         // single barrier per chunk
        if (c + 2 < C) issue_loads(c + 2, (c + 2) % NSTAGE);

        const uint32_t stA = sbase + TILE0 + s * STAGE_BYTES;
        const uint32_t stB = stA + TILE_BYTES;

#pragma unroll
        for (int ks = 0; ks < 4; ks++) {
            const uint32_t ko = (uint32_t)(ks * 32);
            uint32_t aq[4][4], bq[2][4];
#pragma unroll
            for (int f = 0; f < 4; f++) ldsm4(aq[f], stA + aBase[f] + ko);
#pragma unroll
            for (int p = 0; p < 2; p++) ldsm4(bq[p], stB + bBase[p] + ko);
#pragma unroll
            for (int f = 0; f < 4; f++)
#pragma unroll
                for (int p = 0; p < 2; p++) {
                    mma_f16(acc[f][2 * p],     aq[f], bq[p][0], bq[p][1]);
                    mma_f16(acc[f][2 * p + 1], aq[f], bq[p][2], bq[p][3]);
                }
        }
    }

    // ---- epilogue: bias + leaky (+wgt / fp16 round), direct stores ----
    const float* bb = bias + e * NCOL + n0;
#pragma unroll
    for (int f = 0; f < 4; f++) {
        const int rbase = warp_m * 64 + f * 16 + qr;
#pragma unroll
        for (int half = 0; half < 2; half++) {
            const int row = rbase + half * 8;
            const int m = m0 + row;
            if (m >= cnt) continue;
            const int grow = off + m;
            float wgt = 0.f;
            if (PASS2) wgt = g_w[grow];
#pragma unroll
            for (int g = 0; g < 4; g++) {
                const int col = warp_n * 32 + g * 8 + qc;
                float v0 = acc[f][g][2 * half + 0] + bb[col];
                float v1 = acc[f][g][2 * half + 1] + bb[col + 1];
                v0 = (v0 > 0.f) ? v0 : 0.01f * v0;
                v1 = (v1 > 0.f) ? v1 : 0.01f * v1;
                const size_t base = (size_t)grow * NCOL + n0 + col;
                if (!PASS2) {
                    *(uint32_t*)&g_hq[base] =
                        (uint32_t)__half_as_ushort(__float2half_rn(v0)) |
                        ((uint32_t)__half_as_ushort(__float2half_rn(v1)) << 16);
                } else {
                    *(float2*)&g_out2[base] = make_float2(wgt * v0, wgt * v1);
                }
            }
        }
    }
}

// ---------------- combine ----------------
__global__ void combine_kernel(float* __restrict__ out) {
    const int t = blockIdx.x * blockDim.x + threadIdx.x;
    if (t >= N_TOK * (D_DIM / 4)) return;
    const int n = t / (D_DIM / 4);
    const int d = (t % (D_DIM / 4)) * 4;
    const int s0 = g_slot[2 * n], s1 = g_slot[2 * n + 1];
    float4 a = *(const float4*)(g_out2 + (size_t)s0 * D_DIM + d);
    float4 b = *(const float4*)(g_out2 + (size_t)s1 * D_DIM + d);
    float4 r; r.x = a.x + b.x; r.y = a.y + b.y; r.z = a.z + b.z; r.w = a.w + b.w;
    *(float4*)(out + (size_t)n * D_DIM + d) = r;
}

extern "C" void kernel_launch(void* const* d_in, const int* in_sizes, int n_in,
                              void* d_out, int out_size) {
    const float* x  = (const float*)d_in[0];
    const float* Wr = (const float*)d_in[1];
    const float* br = (const float*)d_in[2];
    const float* W1 = (const float*)d_in[3];
    const float* b1 = (const float*)d_in[4];
    const float* W2 = (const float*)d_in[5];
    const float* b2 = (const float*)d_in[6];
    float* out = (float*)d_out;

    cudaFuncSetAttribute(gemm_f16<false, D_DIM, H_DIM>,
                         cudaFuncAttributeMaxDynamicSharedMemorySize, SMEM_DYN);
    cudaFuncSetAttribute(gemm_f16<true, H_DIM, D_DIM>,
                         cudaFuncAttributeMaxDynamicSharedMemorySize, SMEM_DYN);

    // REAL device addresses of __device__ scratch (never pass symbols from host!)
    __half *w1q, *w2q;
    cudaGetSymbolAddress((void**)&w1q, g_w1q);
    cudaGetSymbolAddress((void**)&w2q, g_w2q);

    init_kernel<<<1, 32>>>();
    router_kernel<<<RBLK, 256>>>(x, Wr, br);
    offsets_loss_kernel<<<1, 256>>>(out, out_size);
    scatter_kernel<<<(N_TOK + 255) / 256, 256>>>();
    convert_x_kernel<<<(N_TOK * D_DIM / 4 + 255) / 256, 256>>>(x);
    transpose_half_kernel<D_DIM, H_DIM>
        <<<dim3(H_DIM / 32, D_DIM / 32, E_EXP), dim3(32, 8)>>>(W1, w1q);
    transpose_half_kernel<H_DIM, D_DIM>
        <<<dim3(D_DIM / 32, H_DIM / 32, E_EXP), dim3(32, 8)>>>(W2, w2q);

    gemm_f16<false, D_DIM, H_DIM>
        <<<dim3(H_DIM / BN, MAXTILE, 1), 256, SMEM_DYN>>>(b1);
    gemm_f16<true, H_DIM, D_DIM>
        <<<dim3(D_DIM / BN, MAXTILE, 1), 256, SMEM_DYN>>>(b2);
    combine_kernel<<<(N_TOK * D_DIM / 4 + 255) / 256, 256>>>(out);
}

// round 14
// speedup vs baseline: 1.5334x; 1.0432x over previous
#include <cuda_runtime.h>
#include <cuda_fp16.h>
#include <cstdint>

// Problem dims: B=8, T=2048 -> N=16384 tokens, D=512, E=8, H=1024, top_k=2
#define N_TOK   16384
#define D_DIM   512
#define E_EXP   8
#define H_DIM   1024
#define NPAIR   (2 * N_TOK)
#define RBLK    (N_TOK / 8)
#define CAP     N_TOK                 // fixed per-expert segment capacity (top-2 distinct => cnt<=N_TOK)
#define NROW    (E_EXP * CAP)         // 131072 capacity rows

#define BM 128
#define BN 128
#define KCH 64                       // 64 fp16 = 128B of data per row per chunk
#define ROWB 144                     // smem row stride (128B data + 16B pad)
#define TILE_BYTES (128 * ROWB)      // 18432
#define STAGE_BYTES (2 * TILE_BYTES) // A, B = 36864
#define NSTAGE 3
#define SMEM_DYN (1024 + NSTAGE * STAGE_BYTES)   // 111616 B (2 CTAs/SM: 223232 <= 227KB)
#define MAXTILE 264                  // >= 256 + (E_EXP-1) ragged tiles

// ---------------- scratch (static device globals) ----------------
__device__ __align__(1024) __half g_xq[(size_t)N_TOK * D_DIM];
__device__ __align__(1024) __half g_w1q[(size_t)E_EXP * H_DIM * D_DIM]; // [E][H][D] K-major
__device__ __align__(1024) __half g_w2q[(size_t)E_EXP * D_DIM * H_DIM]; // [E][D][H] K-major
__device__ __align__(1024) __half g_hq[(size_t)NROW * H_DIM];           // 268 MB
__device__ __align__(1024) float g_out2[(size_t)NROW * D_DIM];          // 268 MB
__device__ int   g_tok[NROW];
__device__ float g_w[NROW];
__device__ int   g_slot[NPAIR];
__device__ int   g_cnt[E_EXP];                   // zero at load; re-zeroed by combine tail
__device__ int   g_toff[E_EXP + 1];              // tile prefix (ceil(cnt/BM))
__device__ float g_psums[RBLK * E_EXP];

// ---------------- PTX helpers (baseline ISA only) ----------------
__device__ __forceinline__ uint32_t smem_u32(const void* p) {
    uint32_t a;
    asm("{ .reg .u64 t; cvta.to.shared.u64 t, %1; cvt.u32.u64 %0, t; }" : "=r"(a) : "l"(p));
    return a;
}
__device__ __forceinline__ void cp16(uint32_t dst, const void* src) {
    asm volatile("cp.async.cg.shared.global [%0], [%1], 16;" :: "r"(dst), "l"(src));
}
__device__ __forceinline__ void ldsm4(uint32_t* r, uint32_t addr) {
    asm volatile("ldmatrix.sync.aligned.m8n8.x4.shared.b16 {%0,%1,%2,%3}, [%4];"
                 : "=r"(r[0]), "=r"(r[1]), "=r"(r[2]), "=r"(r[3]) : "r"(addr));
}
__device__ __forceinline__ void mma_f16(float* c, const uint32_t* a, uint32_t b0, uint32_t b1) {
    asm volatile(
        "mma.sync.aligned.m16n8k16.row.col.f32.f16.f16.f32 "
        "{%0,%1,%2,%3}, {%4,%5,%6,%7}, {%8,%9}, {%0,%1,%2,%3};"
        : "+f"(c[0]), "+f"(c[1]), "+f"(c[2]), "+f"(c[3])
        : "r"(a[0]), "r"(a[1]), "r"(a[2]), "r"(a[3]), "r"(b0), "r"(b1));
}

// ---------------- router (fused: logits + softmax + top2 + scatter + x->fp16) ----------------
__global__ void router_kernel(const float* __restrict__ x,
                              const float* __restrict__ Wr,
                              const float* __restrict__ br) {
    __shared__ float ps[8][E_EXP];
    const int wid = threadIdx.x >> 5, lane = threadIdx.x & 31;
    const int n = blockIdx.x * 8 + wid;
    const float* xr = x + (size_t)n * D_DIM;
    __half* xq = g_xq + (size_t)n * D_DIM;
    float acc[E_EXP];
#pragma unroll
    for (int e = 0; e < E_EXP; e++) acc[e] = 0.f;
    for (int i = lane; i < D_DIM; i += 32) {       // coalesced on x (R9-proven layout)
        float xv = xr[i];
        xq[i] = __float2half_rn(xv);               // coalesced 64B/warp half stores
        const float* w = Wr + i * E_EXP;
#pragma unroll
        for (int e = 0; e < E_EXP; e++) acc[e] += xv * w[e];
    }
#pragma unroll
    for (int e = 0; e < E_EXP; e++)
#pragma unroll
        for (int o = 16; o > 0; o >>= 1)
            acc[e] += __shfl_xor_sync(0xffffffffu, acc[e], o);

    if (lane == 0) {
        float mx = -1e30f;
#pragma unroll
        for (int e = 0; e < E_EXP; e++) { acc[e] += br[e]; mx = fmaxf(mx, acc[e]); }
        float s = 0.f;
#pragma unroll
        for (int e = 0; e < E_EXP; e++) { acc[e] = expf(acc[e] - mx); s += acc[e]; }
        const float inv = 1.f / s;
        float p1 = -1.f, p2 = -1.f; int i1 = 0, i2 = 0;
#pragma unroll
        for (int e = 0; e < E_EXP; e++) {
            float p = acc[e] * inv;
            ps[wid][e] = p;
            if (p > p1)      { p2 = p1; i2 = i1; p1 = p; i1 = e; }
            else if (p > p2) { p2 = p; i2 = e; }
        }
        // direct scatter into fixed-capacity expert segments
        int pos1 = atomicAdd(&g_cnt[i1], 1);
        int p1i = i1 * CAP + pos1;
        g_tok[p1i] = n; g_w[p1i] = p1; g_slot[2 * n] = p1i;
        int pos2 = atomicAdd(&g_cnt[i2], 1);
        int p2i = i2 * CAP + pos2;
        g_tok[p2i] = n; g_w[p2i] = p2; g_slot[2 * n + 1] = p2i;
    }
    __syncthreads();
    if (threadIdx.x < E_EXP) {
        float s = 0.f;
#pragma unroll
        for (int w = 0; w < 8; w++) s += ps[w][threadIdx.x];
        g_psums[blockIdx.x * E_EXP + threadIdx.x] = s;
    }
}

// ---------------- tile prefix + gating loss ----------------
__global__ void offsets_loss_kernel(float* __restrict__ out, int out_size) {
    __shared__ float dsq[E_EXP];
    const int tid = threadIdx.x;
    if (tid == 0) {
        int t = 0;
        for (int e = 0; e < E_EXP; e++) {
            g_toff[e] = t;
            t += (g_cnt[e] + BM - 1) / BM;
        }
        g_toff[E_EXP] = t;
    }
    const int wid = tid >> 5, lane = tid & 31;
    if (wid < E_EXP) {
        float s = 0.f;
        for (int b = lane; b < RBLK; b += 32) s += g_psums[b * E_EXP + wid];
#pragma unroll
        for (int o = 16; o > 0; o >>= 1) s += __shfl_xor_sync(0xffffffffu, s, o);
        if (lane == 0) {
            float mean = s / (float)N_TOK;
            float d = (1.0f / E_EXP) - mean;
            dsq[wid] = d * d;
        }
    }
    __syncthreads();
    if (tid == 0 && out_size > N_TOK * D_DIM) {
        float l = 0.f;
        for (int e = 0; e < E_EXP; e++) l += dsq[e];
        out[N_TOK * D_DIM] = (l / E_EXP) * 1e-4f;
    }
}

// ---------------- merged weight transpose: W1 and W2 in one launch ----------------
// Th pointers MUST be real device addresses (cudaGetSymbolAddress) — ATS host-shadow trap.
__global__ void transpose_both_kernel(const float* __restrict__ W1,
                                      const float* __restrict__ W2,
                                      __half* __restrict__ T1,
                                      __half* __restrict__ T2) {
    __shared__ float t[32][33];
    const int z = blockIdx.z;
    const bool isW2 = (z >= E_EXP);
    const int e = z & (E_EXP - 1);
    const int K = isW2 ? H_DIM : D_DIM;
    const int N = isW2 ? D_DIM : H_DIM;
    const float* W = isW2 ? W2 : W1;
    __half* T = isW2 ? T2 : T1;
    const int n0 = blockIdx.x * 32, k0 = blockIdx.y * 32;
    if (n0 >= N || k0 >= K) return;
    const int tx = threadIdx.x, ty = threadIdx.y;
    for (int i = ty; i < 32; i += 8)
        t[i][tx] = W[((size_t)e * K + k0 + i) * N + n0 + tx];
    __syncthreads();
    for (int i = ty; i < 32; i += 8) {
        float v = t[tx][i];                       // = in[k0+tx][n0+i]
        T[((size_t)e * N + n0 + i) * K + k0 + tx] = __float2half_rn(v);
    }
}

// ---------------- fp16 single-plane GEMM via mma.m16n8k16.f16 + ldmatrix ----------------
// Flattened grid: blockIdx.y = global m-tile over expert segments (g_toff mapping).
// PASS2=false: h = leaky(gather(xq) @ W1q^T + b1) -> g_hq (fp16), KDIM=512,  NCOL=1024
// PASS2=true : o = w * leaky(hq @ W2q^T + b2)     -> g_out2,      KDIM=1024, NCOL=512
template <bool PASS2, int KDIM, int NCOL>
__global__ void __launch_bounds__(256, 2)
gemm_f16(const float* __restrict__ bias) {
    extern __shared__ char smem[];
    const int ty = blockIdx.y;
    if (ty >= g_toff[E_EXP]) return;
    int e = 0;
#pragma unroll
    for (int i = 1; i < E_EXP; i++) if (ty >= g_toff[i]) e = i;
    const int cnt = g_cnt[e];
    const int m0 = (ty - g_toff[e]) * BM;
    const int n0 = blockIdx.x * BN;
    const int off = e * CAP;
    const int tid = threadIdx.x;
    const int wid = tid >> 5, lane = tid & 31;
    const int warp_m = wid >> 2;                 // 0..1 (64 rows)
    const int warp_n = wid & 3;                  // 0..3 (32 cols)
    const int qr = lane >> 2;                    // 0..7
    const int qc = (lane & 3) * 2;               // k/col element pair base

    const uint32_t sbase = smem_u32(smem);
    int* toks = (int*)smem;                      // [0,512)
    const uint32_t TILE0 = 1024;

    if (!PASS2) {
        if (tid < BM) {
            int m = m0 + tid;
            toks[tid] = g_tok[off + (m < cnt ? m : cnt - 1)];
        }
        __syncthreads();
    }

    const char* Aqb = (const char*)(PASS2 ? g_hq : g_xq);
    const char* Bqb = (const char*)(PASS2 ? g_w2q : g_w1q);

    // cp.async plan: 4 units of 16B per tile type (128 rows x 8 units)
    size_t aoff[4], boff[4];
    uint32_t dst[4];
#pragma unroll
    for (int t = 0; t < 4; t++) {
        int uu = tid + 256 * t;
        int r = uu >> 3, u = uu & 7;
        dst[t] = (uint32_t)(r * ROWB + u * 16);
        if (!PASS2) {
            aoff[t] = ((size_t)toks[r] * KDIM) * 2 + u * 16;
        } else {
            int m = m0 + r;
            int row = off + (m < cnt ? m : cnt - 1);
            aoff[t] = ((size_t)row * KDIM) * 2 + u * 16;
        }
        boff[t] = ((size_t)(e * NCOL + n0 + r) * KDIM) * 2 + u * 16;
    }

    auto issue_loads = [&](int c, int s) {
        const uint32_t st = sbase + TILE0 + s * STAGE_BYTES;
        const size_t kb = (size_t)c * (KCH * 2);
#pragma unroll
        for (int t = 0; t < 4; t++) {
            cp16(st + dst[t],              Aqb + aoff[t] + kb);
            cp16(st + TILE_BYTES + dst[t], Bqb + boff[t] + kb);
        }
        asm volatile("cp.async.commit_group;" ::: "memory");
    };

    float acc[4][4][4];
#pragma unroll
    for (int f = 0; f < 4; f++)
#pragma unroll
        for (int g = 0; g < 4; g++)
#pragma unroll
            for (int q = 0; q < 4; q++) acc[f][g][q] = 0.f;

    constexpr int C = KDIM / KCH;
    issue_loads(0, 0);
    issue_loads(1, 1);

    // ldmatrix per-thread base offsets (within a tile; add stage base + ks*32)
    uint32_t aBase[4];
#pragma unroll
    for (int f = 0; f < 4; f++)
        aBase[f] = (uint32_t)((warp_m * 64 + f * 16 + (lane & 15)) * ROWB + (lane >> 4) * 16);
    uint32_t bBase[2];
#pragma unroll
    for (int p = 0; p < 2; p++)
        bBase[p] = (uint32_t)((warp_n * 32 + p * 16 + ((lane >> 4) & 1) * 8 + (lane & 7)) * ROWB
                              + ((lane >> 3) & 1) * 16);

    for (int c = 0; c < C; c++) {
        const int s = c % NSTAGE;
        if (c == C - 1) asm volatile("cp.async.wait_group 0;" ::: "memory");
        else            asm volatile("cp.async.wait_group 1;" ::: "memory");
        __syncthreads();                         // single barrier per chunk
        if (c + 2 < C) issue_loads(c + 2, (c + 2) % NSTAGE);

        const uint32_t stA = sbase + TILE0 + s * STAGE_BYTES;
        const uint32_t stB = stA + TILE_BYTES;

#pragma unroll
        for (int ks = 0; ks < 4; ks++) {
            const uint32_t ko = (uint32_t)(ks * 32);
            uint32_t aq[4][4], bq[2][4];
#pragma unroll
            for (int f = 0; f < 4; f++) ldsm4(aq[f], stA + aBase[f] + ko);
#pragma unroll
            for (int p = 0; p < 2; p++) ldsm4(bq[p], stB + bBase[p] + ko);
#pragma unroll
            for (int f = 0; f < 4; f++)
#pragma unroll
                for (int p = 0; p < 2; p++) {
                    mma_f16(acc[f][2 * p],     aq[f], bq[p][0], bq[p][1]);
                    mma_f16(acc[f][2 * p + 1], aq[f], bq[p][2], bq[p][3]);
                }
        }
    }

    // ---- epilogue: bias + leaky (+wgt / fp16 round), direct stores ----
    const float* bb = bias + e * NCOL + n0;
#pragma unroll
    for (int f = 0; f < 4; f++) {
        const int rbase = warp_m * 64 + f * 16 + qr;
#pragma unroll
        for (int half = 0; half < 2; half++) {
            const int row = rbase + half * 8;
            const int m = m0 + row;
            if (m >= cnt) continue;
            const int grow = off + m;
            float wgt = 0.f;
            if (PASS2) wgt = g_w[grow];
#pragma unroll
            for (int g = 0; g < 4; g++) {
                const int col = warp_n * 32 + g * 8 + qc;
                float v0 = acc[f][g][2 * half + 0] + bb[col];
                float v1 = acc[f][g][2 * half + 1] + bb[col + 1];
                v0 = (v0 > 0.f) ? v0 : 0.01f * v0;
                v1 = (v1 > 0.f) ? v1 : 0.01f * v1;
                const size_t base = (size_t)grow * NCOL + n0 + col;
                if (!PASS2) {
                    *(uint32_t*)&g_hq[base] =
                        (uint32_t)__half_as_ushort(__float2half_rn(v0)) |
                        ((uint32_t)__half_as_ushort(__float2half_rn(v1)) << 16);
                } else {
                    *(float2*)&g_out2[base] = make_float2(wgt * v0, wgt * v1);
                }
            }
        }
    }
}

// ---------------- combine (+ re-zero g_cnt for the next invocation) ----------------
__global__ void combine_kernel(float* __restrict__ out) {
    const int t = blockIdx.x * blockDim.x + threadIdx.x;
    if (blockIdx.x == 0 && threadIdx.x < E_EXP) g_cnt[threadIdx.x] = 0;
    if (t >= N_TOK * (D_DIM / 4)) return;
    const int n = t / (D_DIM / 4);
    const int d = (t % (D_DIM / 4)) * 4;
    const int s0 = g_slot[2 * n], s1 = g_slot[2 * n + 1];
    float4 a = *(const float4*)(g_out2 + (size_t)s0 * D_DIM + d);
    float4 b = *(const float4*)(g_out2 + (size_t)s1 * D_DIM + d);
    float4 r; r.x = a.x + b.x; r.y = a.y + b.y; r.z = a.z + b.z; r.w = a.w + b.w;
    *(float4*)(out + (size_t)n * D_DIM + d) = r;
}

extern "C" void kernel_launch(void* const* d_in, const int* in_sizes, int n_in,
                              void* d_out, int out_size) {
    const float* x  = (const float*)d_in[0];
    const float* Wr = (const float*)d_in[1];
    const float* br = (const float*)d_in[2];
    const float* W1 = (const float*)d_in[3];
    const float* b1 = (const float*)d_in[4];
    const float* W2 = (const float*)d_in[5];
    const float* b2 = (const float*)d_in[6];
    float* out = (float*)d_out;

    cudaFuncSetAttribute(gemm_f16<false, D_DIM, H_DIM>,
                         cudaFuncAttributeMaxDynamicSharedMemorySize, SMEM_DYN);
    cudaFuncSetAttribute(gemm_f16<true, H_DIM, D_DIM>,
                         cudaFuncAttributeMaxDynamicSharedMemorySize, SMEM_DYN);

    // REAL device addresses of __device__ scratch (never pass symbols from host!)
    __half *w1q, *w2q;
    cudaGetSymbolAddress((void**)&w1q, g_w1q);
    cudaGetSymbolAddress((void**)&w2q, g_w2q);

    router_kernel<<<RBLK, 256>>>(x, Wr, br);
    offsets_loss_kernel<<<1, 256>>>(out, out_size);
    transpose_both_kernel<<<dim3(32, 32, 2 * E_EXP), dim3(32, 8)>>>(W1, W2, w1q, w2q);
    gemm_f16<false, D_DIM, H_DIM>
        <<<dim3(H_DIM / BN, MAXTILE, 1), 256, SMEM_DYN>>>(b1);
    gemm_f16<true, H_DIM, D_DIM>
        <<<dim3(D_DIM / BN, MAXTILE, 1), 256, SMEM_DYN>>>(b2);
    combine_kernel<<<(N_TOK * D_DIM / 4 + 255) / 256, 256>>>(out);
}